// round 8
// baseline (speedup 1.0000x reference)
#include <cuda_runtime.h>

__device__ float g_part[64 * 9216];   // stage-1 partials [z][i*1152+c]
__device__ float g_xs[9216];          // fully-reduced xs, e = i*1152 + c
__device__ float g_us[184320];        // batch-summed u_hat [c*160 + u*16 + s]
__device__ float g_usq[11520];        // ||u_sum||^2 per (c,u)
__device__ float g_k[11520];          // final scale per (c,u)

// A1: g_part[z][e] = sum of batches z*4..z*4+3.  x as [256,2304] float4.
__global__ void __launch_bounds__(256) reduce_x1_kernel(const float* __restrict__ x) {
    const int col = blockIdx.x * 256 + threadIdx.x;   // 0..2303
    const int z = blockIdx.y;                         // 0..63
    const float4* p = reinterpret_cast<const float4*>(x) + (size_t)(z * 4) * 2304 + col;
    const float4 v0 = __ldg(p);
    const float4 v1 = __ldg(p + 2304);
    const float4 v2 = __ldg(p + 2 * 2304);
    const float4 v3 = __ldg(p + 3 * 2304);
    float4 a;
    a.x = (v0.x + v1.x) + (v2.x + v3.x);
    a.y = (v0.y + v1.y) + (v2.y + v3.y);
    a.z = (v0.z + v1.z) + (v2.z + v3.z);
    a.w = (v0.w + v1.w) + (v2.w + v3.w);
    reinterpret_cast<float4*>(g_part)[(size_t)z * 2304 + col] = a;
}

// A2: g_xs[e] = sum_z g_part[z][e]. 16 named accumulators -> MLP 16.
__global__ void __launch_bounds__(256) reduce_x2_kernel() {
    const int e = blockIdx.x * 256 + threadIdx.x;     // 0..9215 (36 blocks)
    float acc[16];
    #pragma unroll
    for (int j = 0; j < 16; ++j) acc[j] = g_part[(size_t)j * 9216 + e];
    #pragma unroll
    for (int r = 1; r < 4; ++r) {
        #pragma unroll
        for (int j = 0; j < 16; ++j)
            acc[j] += g_part[(size_t)(r * 16 + j) * 9216 + e];
    }
    float s = 0.f;
    #pragma unroll
    for (int j = 0; j < 16; ++j) s += acc[j];
    g_xs[e] = s;
}

// B: pure stream. Thread per output element e = c*160 + u*16 + s.
// us[e] = dot(W[e*8..], xs[:,c]); usq via 4 xor-shuffles in the 16-lane group.
__global__ void __launch_bounds__(256) us_kernel(const float* __restrict__ W) {
    const int e = blockIdx.x * 256 + threadIdx.x;     // 0..184319 (720 blocks)
    const int c = e / 160;
    const int r = e - c * 160;                        // u*16 + s

    const float4* wp = reinterpret_cast<const float4*>(W) + (size_t)e * 2;
    const float4 w0 = __ldg(wp);
    const float4 w1 = __ldg(wp + 1);

    const float* xp = g_xs + c;                       // broadcast within lane groups
    const float us = w0.x * xp[0]        + w0.y * xp[1152]
                   + w0.z * xp[2 * 1152] + w0.w * xp[3 * 1152]
                   + w1.x * xp[4 * 1152] + w1.y * xp[5 * 1152]
                   + w1.z * xp[6 * 1152] + w1.w * xp[7 * 1152];
    g_us[e] = us;

    // ||u_sum||^2 over the 16 s-lanes (16-aligned groups within the warp)
    float q = us * us;
    q += __shfl_xor_sync(0xffffffffu, q, 1);
    q += __shfl_xor_sync(0xffffffffu, q, 2);
    q += __shfl_xor_sync(0xffffffffu, q, 4);
    q += __shfl_xor_sync(0xffffffffu, q, 8);
    if ((r & 15) == 0)
        g_usq[c * 10 + (r >> 4)] = q;
}

// C: one THREAD per capsule. All 10 u's in registers; zero shuffles/barriers.
// Scalar recurrence: msq = cij^2*usq, coef = msq/(1+msq)/|s|, k = coef*cij.
__global__ void __launch_bounds__(128) routing_kernel() {
    const int c = blockIdx.x * 128 + threadIdx.x;     // 9 blocks * 128 = 1152

    float usq[10], b[10], cij[10], k[10];
    #pragma unroll
    for (int u = 0; u < 10; ++u) {
        usq[u] = g_usq[c * 10 + u];
        b[u] = 0.f;
        cij[u] = 0.1f;                                // softmax(0) exactly
    }

    #pragma unroll
    for (int it = 0; it < 3; ++it) {
        #pragma unroll
        for (int u = 0; u < 10; ++u) {
            const float msq = cij[u] * cij[u] * usq[u];
            const float coef = msq / (1.0f + msq) * rsqrtf(msq);
            k[u] = coef * cij[u];
        }
        if (it < 2) {
            float m = -1e30f;
            #pragma unroll
            for (int u = 0; u < 10; ++u) {
                b[u] += k[u] * usq[u] * (1.0f / 256.0f);
                m = fmaxf(m, b[u]);
            }
            float ex[10], d = 0.f;
            #pragma unroll
            for (int u = 0; u < 10; ++u) { ex[u] = __expf(b[u] - m); d += ex[u]; }
            const float inv = 1.0f / d;
            #pragma unroll
            for (int u = 0; u < 10; ++u) cij[u] = ex[u] * inv;
        }
    }

    #pragma unroll
    for (int u = 0; u < 10; ++u) g_k[c * 10 + u] = k[u];
}

// D: out = k[c,u] * us, float4 elementwise (46080 float4s, 180 blocks).
__global__ void __launch_bounds__(256) scale_kernel(float* __restrict__ out) {
    const int g = blockIdx.x * 256 + threadIdx.x;     // float4 index, 0..46079
    const int c = g / 40;
    const int u = (g - c * 40) >> 2;
    const float k = g_k[c * 10 + u];                  // broadcast across 4 lanes
    const float4 v = reinterpret_cast<const float4*>(g_us)[g];
    reinterpret_cast<float4*>(out)[g] = make_float4(k * v.x, k * v.y, k * v.z, k * v.w);
}

extern "C" void kernel_launch(void* const* d_in, const int* in_sizes, int n_in,
                              void* d_out, int out_size) {
    const float* x = (const float*)d_in[0];   // [256, 8, 1152]
    const float* W = (const float*)d_in[1];   // [1, 1152, 10, 16, 8]
    float* out = (float*)d_out;               // [1152, 10, 16]

    reduce_x1_kernel<<<dim3(9, 64), 256>>>(x);
    reduce_x2_kernel<<<36, 256>>>();
    us_kernel<<<720, 256>>>(W);
    routing_kernel<<<9, 128>>>();
    scale_kernel<<<180, 256>>>(out);
}

// round 9
// speedup vs baseline: 1.1335x; 1.1335x over previous
#include <cuda_runtime.h>

__device__ float g_part[64 * 9216];   // stage-1 partials [z][i*1152+c]
__device__ float g_xs[9216];          // fully-reduced xs, e = i*1152 + c
__device__ float g_us[184320];        // batch-summed u_hat [c*160 + u*16 + s]
__device__ float g_usq[11520];        // ||u_sum||^2 per (c,u)

// A1: g_part[z][e] = sum of batches z*4..z*4+3.  x as [256,2304] float4.
__global__ void __launch_bounds__(256) reduce_x1_kernel(const float* __restrict__ x) {
    const int col = blockIdx.x * 256 + threadIdx.x;   // 0..2303
    const int z = blockIdx.y;                         // 0..63
    const float4* p = reinterpret_cast<const float4*>(x) + (size_t)(z * 4) * 2304 + col;
    const float4 v0 = __ldg(p);
    const float4 v1 = __ldg(p + 2304);
    const float4 v2 = __ldg(p + 2 * 2304);
    const float4 v3 = __ldg(p + 3 * 2304);
    float4 a;
    a.x = (v0.x + v1.x) + (v2.x + v3.x);
    a.y = (v0.y + v1.y) + (v2.y + v3.y);
    a.z = (v0.z + v1.z) + (v2.z + v3.z);
    a.w = (v0.w + v1.w) + (v2.w + v3.w);
    reinterpret_cast<float4*>(g_part)[(size_t)z * 2304 + col] = a;
}

// A2: g_xs[e] = sum_z g_part[z][e]. 8 named accumulators, 8 rounds (MLP 8).
__global__ void __launch_bounds__(256) reduce_x2_kernel() {
    const int e = blockIdx.x * 256 + threadIdx.x;     // 0..9215 (36 blocks)
    float a0 = 0.f, a1 = 0.f, a2 = 0.f, a3 = 0.f;
    float a4 = 0.f, a5 = 0.f, a6 = 0.f, a7 = 0.f;
    #pragma unroll
    for (int r = 0; r < 8; ++r) {
        const float* p = g_part + (size_t)(r * 8) * 9216 + e;
        a0 += p[0];        a1 += p[9216];     a2 += p[2 * 9216]; a3 += p[3 * 9216];
        a4 += p[4 * 9216]; a5 += p[5 * 9216]; a6 += p[6 * 9216]; a7 += p[7 * 9216];
    }
    g_xs[e] = ((a0 + a1) + (a2 + a3)) + ((a4 + a5) + (a6 + a7));
}

// B: pure stream. Thread per element e = c*160 + u*16 + s.
// us[e] = dot(W[e*8..], xs[:,c]); usq via 4 xor-shuffles in the 16-lane group.
__global__ void __launch_bounds__(256) us_kernel(const float* __restrict__ W) {
    const int e = blockIdx.x * 256 + threadIdx.x;     // 0..184319 (720 blocks)
    const int c = e / 160;
    const int r = e - c * 160;                        // u*16 + s

    const float4* wp = reinterpret_cast<const float4*>(W) + (size_t)e * 2;
    const float4 w0 = __ldg(wp);
    const float4 w1 = __ldg(wp + 1);

    const float* xp = g_xs + c;                       // broadcast within lane groups
    const float us = w0.x * xp[0]        + w0.y * xp[1152]
                   + w0.z * xp[2 * 1152] + w0.w * xp[3 * 1152]
                   + w1.x * xp[4 * 1152] + w1.y * xp[5 * 1152]
                   + w1.z * xp[6 * 1152] + w1.w * xp[7 * 1152];
    g_us[e] = us;

    float q = us * us;
    q += __shfl_xor_sync(0xffffffffu, q, 1);
    q += __shfl_xor_sync(0xffffffffu, q, 2);
    q += __shfl_xor_sync(0xffffffffu, q, 4);
    q += __shfl_xor_sync(0xffffffffu, q, 8);
    if ((r & 15) == 0)
        g_usq[c * 10 + (r >> 4)] = q;
}

// C: routing + scale. One THREAD per (c,u), u in 16-lane groups (u<10 valid).
// All per-u state is scalar (no register arrays -> no spills). Softmax over u
// = 8 xor-shuffles per iteration within the 16-lane group. Then each valid
// thread rescales its 16 us-values (L2 hits) into the output.
__global__ void __launch_bounds__(256) routing_scale_kernel(float* __restrict__ out) {
    const int t = blockIdx.x * 256 + threadIdx.x;     // 0..18431 (72 blocks)
    const int c = t >> 4;                             // 0..1151
    const int u = t & 15;
    const bool valid = (u < 10);

    const float usq = valid ? g_usq[c * 10 + u] : 0.f;
    float b = valid ? 0.f : -1e30f;                   // pad lanes never win max
    float cij = 0.1f;                                 // softmax of zeros, exact
    float k = 0.f;

    #pragma unroll
    for (int it = 0; it < 3; ++it) {
        const float msq = cij * cij * usq;
        const float coef = msq / (1.0f + msq) * rsqrtf(msq);
        k = coef * cij;

        if (it < 2) {
            if (valid) b += k * usq * (1.0f / 256.0f);
            float m = b;
            m = fmaxf(m, __shfl_xor_sync(0xffffffffu, m, 8));
            m = fmaxf(m, __shfl_xor_sync(0xffffffffu, m, 4));
            m = fmaxf(m, __shfl_xor_sync(0xffffffffu, m, 2));
            m = fmaxf(m, __shfl_xor_sync(0xffffffffu, m, 1));
            const float e = valid ? __expf(b - m) : 0.f;
            float d = e;
            d += __shfl_xor_sync(0xffffffffu, d, 8);
            d += __shfl_xor_sync(0xffffffffu, d, 4);
            d += __shfl_xor_sync(0xffffffffu, d, 2);
            d += __shfl_xor_sync(0xffffffffu, d, 1);
            cij = e / d;
        }
    }

    if (valid) {
        const float4* up = reinterpret_cast<const float4*>(g_us + (size_t)c * 160 + u * 16);
        float4* op = reinterpret_cast<float4*>(out + (size_t)c * 160 + u * 16);
        const float4 q0 = up[0], q1 = up[1], q2 = up[2], q3 = up[3];
        op[0] = make_float4(k * q0.x, k * q0.y, k * q0.z, k * q0.w);
        op[1] = make_float4(k * q1.x, k * q1.y, k * q1.z, k * q1.w);
        op[2] = make_float4(k * q2.x, k * q2.y, k * q2.z, k * q2.w);
        op[3] = make_float4(k * q3.x, k * q3.y, k * q3.z, k * q3.w);
    }
}

extern "C" void kernel_launch(void* const* d_in, const int* in_sizes, int n_in,
                              void* d_out, int out_size) {
    const float* x = (const float*)d_in[0];   // [256, 8, 1152]
    const float* W = (const float*)d_in[1];   // [1, 1152, 10, 16, 8]
    float* out = (float*)d_out;               // [1152, 10, 16]

    reduce_x1_kernel<<<dim3(9, 64), 256>>>(x);
    reduce_x2_kernel<<<36, 256>>>();
    us_kernel<<<720, 256>>>(W);
    routing_scale_kernel<<<72, 256>>>(out);
}

// round 10
// speedup vs baseline: 1.6512x; 1.4568x over previous
#include <cuda_runtime.h>

// Stage-1 partial batch sums of x: [z=64][i*1152+c]  (2.36 MB)
__device__ float g_part[64 * 9216];

// A: g_part[z][e] = sum of batches z*4..z*4+3.  x viewed as [256,2304] float4.
__global__ void __launch_bounds__(256) reduce_x1_kernel(const float* __restrict__ x) {
    const int col = blockIdx.x * 256 + threadIdx.x;   // 0..2303
    const int z = blockIdx.y;                         // 0..63
    const float4* p = reinterpret_cast<const float4*>(x) + (size_t)(z * 4) * 2304 + col;
    const float4 v0 = __ldg(p);
    const float4 v1 = __ldg(p + 2304);
    const float4 v2 = __ldg(p + 2 * 2304);
    const float4 v3 = __ldg(p + 3 * 2304);
    float4 a;
    a.x = (v0.x + v1.x) + (v2.x + v3.x);
    a.y = (v0.y + v1.y) + (v2.y + v3.y);
    a.z = (v0.z + v1.z) + (v2.z + v3.z);
    a.w = (v0.w + v1.w) + (v2.w + v3.w);
    reinterpret_cast<float4*>(g_part)[(size_t)z * 2304 + col] = a;
}

// B: fully fused. One block = 2 capsules (320 threads = 10 warps).
// Thread t -> element (capsule lc = t/160, u = r>>4, s = r&15).
//   1. xs for both capsules from the 64 z-partials (smem tree)
//   2. us = dot(W row, xs)  (2 coalesced LDG.128 per thread)
//   3. usq = ||u_sum||^2 per (c,u) via 4 in-group shuffles
//   4. scalar routing recurrence on threads t<20 (smem-coupled softmax)
//   5. out = k * us from registers
__global__ void __launch_bounds__(320) fused_kernel(const float* __restrict__ W,
                                                    float* __restrict__ out) {
    const int t = threadIdx.x;            // 0..319
    const int c0 = blockIdx.x * 2;        // 576 blocks -> capsules c0, c0+1

    __shared__ float sm_part[256];
    __shared__ float sm_xs[16];           // [lc*8 + i]
    __shared__ float sm_usq[20];          // [lc*10 + u]
    __shared__ float sm_b[20];
    __shared__ float sm_e[20];
    __shared__ float sm_k[20];

    const int lc = (t >= 160) ? 1 : 0;
    const int r = t - lc * 160;           // u*16 + s
    const int u = r >> 4;

    // Kick off the W stream immediately (coalesced: 2 LDG.128 / thread).
    const size_t e = (size_t)blockIdx.x * 320 + t;
    const float4* wp = reinterpret_cast<const float4*>(W) + e * 2;
    const float4 w0 = __ldg(wp);
    const float4 w1 = __ldg(wp + 1);

    // xs: 16 (lc,i) values, each = sum of 64 z-partials. 256 threads:
    // value v = t&15, chunk = t>>4 sums 4 consecutive z (independent L2 loads).
    if (t < 256) {
        const int v = t & 15;
        const int cc = c0 + (v >> 3);
        const int i = v & 7;
        const float* p = g_part + (size_t)((t >> 4) * 4) * 9216 + i * 1152 + cc;
        sm_part[t] = (p[0] + p[9216]) + (p[2 * 9216] + p[3 * 9216]);
    }
    __syncthreads();
    if (t < 16) {
        float a = 0.f;
        #pragma unroll
        for (int j = 0; j < 16; ++j) a += sm_part[t + 16 * j];
        sm_xs[t] = a;
    }
    __syncthreads();

    // us for this element (xs broadcast from smem)
    const float* xp = sm_xs + lc * 8;
    const float us = w0.x * xp[0] + w0.y * xp[1] + w0.z * xp[2] + w0.w * xp[3]
                   + w1.x * xp[4] + w1.y * xp[5] + w1.z * xp[6] + w1.w * xp[7];

    // ||u_sum||^2 over the 16 s-lanes of this (c,u) group
    float q = us * us;
    q += __shfl_xor_sync(0xffffffffu, q, 1);
    q += __shfl_xor_sync(0xffffffffu, q, 2);
    q += __shfl_xor_sync(0xffffffffu, q, 4);
    q += __shfl_xor_sync(0xffffffffu, q, 8);
    if ((t & 15) == 0) sm_usq[lc * 10 + u] = q;
    __syncthreads();

    // Scalar routing on threads 0..19 (t = cc*10 + uu), all inside warp 0.
    if (t < 20) {
        const int cc = (t >= 10) ? 1 : 0;
        const float usq = sm_usq[t];
        float b = 0.f;
        float cij = 0.1f;                 // softmax of zero logits, exact
        float k = 0.f;

        #pragma unroll
        for (int it = 0; it < 3; ++it) {
            const float msq = cij * cij * usq;
            const float coef = msq / (1.0f + msq) * rsqrtf(msq);
            k = coef * cij;

            if (it < 2) {
                b += k * usq * (1.0f / 256.0f);
                sm_b[t] = b;
                __syncwarp(0x000FFFFFu);
                const float* bb = sm_b + cc * 10;
                float m = bb[0];
                #pragma unroll
                for (int j = 1; j < 10; ++j) m = fmaxf(m, bb[j]);
                const float ex = __expf(b - m);
                sm_e[t] = ex;
                __syncwarp(0x000FFFFFu);
                const float* ep = sm_e + cc * 10;
                float d = ep[0];
                #pragma unroll
                for (int j = 1; j < 10; ++j) d += ep[j];
                cij = ex / d;
            }
        }
        sm_k[t] = k;
    }
    __syncthreads();

    // Final scale from registers; coalesced 4B stores.
    out[e] = sm_k[lc * 10 + u] * us;
}

extern "C" void kernel_launch(void* const* d_in, const int* in_sizes, int n_in,
                              void* d_out, int out_size) {
    const float* x = (const float*)d_in[0];   // [256, 8, 1152]
    const float* W = (const float*)d_in[1];   // [1, 1152, 10, 16, 8]
    float* out = (float*)d_out;               // [1152, 10, 16]

    reduce_x1_kernel<<<dim3(9, 64), 256>>>(x);
    fused_kernel<<<576, 320>>>(W, out);
}

// round 11
// speedup vs baseline: 1.9742x; 1.1956x over previous
#include <cuda_runtime.h>

// Stage-1 partial batch sums of x: [z=16][i*1152+c]  (590 KB)
__device__ float g_part[16 * 9216];

// A: g_part[z][e] = sum of batches z*16..z*16+15.  x viewed as [256,2304] float4.
// 4 named float4 accumulators -> 4 loads in flight, 4 dependent rounds.
__global__ void __launch_bounds__(256) reduce_x1_kernel(const float* __restrict__ x) {
    const int col = blockIdx.x * 256 + threadIdx.x;   // 0..2303
    const int z = blockIdx.y;                         // 0..15
    const float4* p = reinterpret_cast<const float4*>(x) + (size_t)(z * 16) * 2304 + col;

    float4 a0 = __ldg(p);
    float4 a1 = __ldg(p + 2304);
    float4 a2 = __ldg(p + 2 * 2304);
    float4 a3 = __ldg(p + 3 * 2304);
    #pragma unroll
    for (int r = 1; r < 4; ++r) {
        const float4 v0 = __ldg(p + (size_t)(r * 4) * 2304);
        const float4 v1 = __ldg(p + (size_t)(r * 4 + 1) * 2304);
        const float4 v2 = __ldg(p + (size_t)(r * 4 + 2) * 2304);
        const float4 v3 = __ldg(p + (size_t)(r * 4 + 3) * 2304);
        a0.x += v0.x; a0.y += v0.y; a0.z += v0.z; a0.w += v0.w;
        a1.x += v1.x; a1.y += v1.y; a1.z += v1.z; a1.w += v1.w;
        a2.x += v2.x; a2.y += v2.y; a2.z += v2.z; a2.w += v2.w;
        a3.x += v3.x; a3.y += v3.y; a3.z += v3.z; a3.w += v3.w;
    }
    float4 a;
    a.x = (a0.x + a1.x) + (a2.x + a3.x);
    a.y = (a0.y + a1.y) + (a2.y + a3.y);
    a.z = (a0.z + a1.z) + (a2.z + a3.z);
    a.w = (a0.w + a1.w) + (a2.w + a3.w);
    reinterpret_cast<float4*>(g_part)[(size_t)z * 2304 + col] = a;
}

// B: fully fused. One block = 2 capsules (320 threads = 10 warps).
//   1. xs for both capsules: ONE partial load per thread (16 chunks x 16 vals)
//   2. us = dot(W row, xs)  (2 coalesced LDG.128 per thread)
//   3. usq per (c,u) via 4 in-group shuffles
//   4. scalar routing recurrence on threads t<20 (smem-coupled softmax)
//   5. out = k * us from registers
__global__ void __launch_bounds__(320) fused_kernel(const float* __restrict__ W,
                                                    float* __restrict__ out) {
    const int t = threadIdx.x;            // 0..319
    const int c0 = blockIdx.x * 2;        // 576 blocks -> capsules c0, c0+1

    __shared__ float sm_part[256];        // [chunk*16 + v]
    __shared__ float sm_xs[16];           // [lc*8 + i]
    __shared__ float sm_usq[20];
    __shared__ float sm_b[20];
    __shared__ float sm_e[20];
    __shared__ float sm_k[20];

    const int lc = (t >= 160) ? 1 : 0;
    const int r = t - lc * 160;           // u*16 + s
    const int u = r >> 4;

    // Kick off the W stream immediately (coalesced: 2 LDG.128 / thread).
    const size_t e = (size_t)blockIdx.x * 320 + t;
    const float4* wp = reinterpret_cast<const float4*>(W) + e * 2;
    const float4 w0 = __ldg(wp);
    const float4 w1 = __ldg(wp + 1);

    // xs partials: one load per thread. v = t&15 -> (cc = c0 + (v>>3), i = v&7);
    // chunk = t>>4. Adjacent threads hit adjacent capsules -> paired sectors.
    if (t < 256) {
        const int v = t & 15;
        const int cc = c0 + (v >> 3);
        const int i = v & 7;
        sm_part[t] = g_part[(size_t)(t >> 4) * 9216 + i * 1152 + cc];
    }
    __syncthreads();
    if (t < 16) {
        float a = 0.f;
        #pragma unroll
        for (int ch = 0; ch < 16; ++ch) a += sm_part[ch * 16 + t];
        sm_xs[t] = a;
    }
    __syncthreads();

    // us for this element (xs broadcast from smem)
    const float* xp = sm_xs + lc * 8;
    const float us = w0.x * xp[0] + w0.y * xp[1] + w0.z * xp[2] + w0.w * xp[3]
                   + w1.x * xp[4] + w1.y * xp[5] + w1.z * xp[6] + w1.w * xp[7];

    // ||u_sum||^2 over the 16 s-lanes of this (c,u) group
    float q = us * us;
    q += __shfl_xor_sync(0xffffffffu, q, 1);
    q += __shfl_xor_sync(0xffffffffu, q, 2);
    q += __shfl_xor_sync(0xffffffffu, q, 4);
    q += __shfl_xor_sync(0xffffffffu, q, 8);
    if ((t & 15) == 0) sm_usq[lc * 10 + u] = q;
    __syncthreads();

    // Scalar routing on threads 0..19 (t = cc*10 + uu), all inside warp 0.
    if (t < 20) {
        const int cc = (t >= 10) ? 1 : 0;
        const float usq = sm_usq[t];
        float b = 0.f;
        float cij = 0.1f;                 // softmax of zero logits, exact
        float k = 0.f;

        #pragma unroll
        for (int it = 0; it < 3; ++it) {
            const float msq = cij * cij * usq;
            const float coef = msq / (1.0f + msq) * rsqrtf(msq);
            k = coef * cij;

            if (it < 2) {
                b += k * usq * (1.0f / 256.0f);
                sm_b[t] = b;
                __syncwarp(0x000FFFFFu);
                const float* bb = sm_b + cc * 10;
                float m = bb[0];
                #pragma unroll
                for (int j = 1; j < 10; ++j) m = fmaxf(m, bb[j]);
                const float ex = __expf(b - m);
                sm_e[t] = ex;
                __syncwarp(0x000FFFFFu);
                const float* ep = sm_e + cc * 10;
                float d = ep[0];
                #pragma unroll
                for (int j = 1; j < 10; ++j) d += ep[j];
                cij = ex / d;
            }
        }
        sm_k[t] = k;
    }
    __syncthreads();

    // Final scale from registers; coalesced 4B stores.
    out[e] = sm_k[lc * 10 + u] * us;
}

extern "C" void kernel_launch(void* const* d_in, const int* in_sizes, int n_in,
                              void* d_out, int out_size) {
    const float* x = (const float*)d_in[0];   // [256, 8, 1152]
    const float* W = (const float*)d_in[1];   // [1, 1152, 10, 16, 8]
    float* out = (float*)d_out;               // [1152, 10, 16]

    reduce_x1_kernel<<<dim3(9, 16), 256>>>(x);
    fused_kernel<<<576, 320>>>(W, out);
}